// round 4
// baseline (speedup 1.0000x reference)
#include <cuda_runtime.h>
#include <cstdint>

#define S_LEN 200
#define BATCH 1024
#define HID   128
#define VOCAB 100000
#define NB    7

// ---------------- scratch (device globals; no allocation) ----------------
__device__ float g_E[(size_t)S_LEN * BATCH * HID];   // ~105 MB: E = x_emb @ W_ih^T + biases
__device__ float g_w[(size_t)S_LEN * BATCH];         // pooling weights [S,B]
__device__ float g_wsum[BATCH];
__device__ float g_outpu[(size_t)BATCH * 2 * HID];   // [B, 256] = [out_w | p_u]

// ---------------- kernel 1: pooling weights ----------------
__global__ void pool_weights_kernel(const float* __restrict__ t,
                                    const float* __restrict__ sxy,
                                    const int* __restrict__ length,
                                    float* __restrict__ w,
                                    float* __restrict__ wsum)
{
    int b = blockIdx.x * blockDim.x + threadIdx.x;
    if (b >= BATCH) return;
    int len = length[b];
    float t_last = t[(size_t)(len - 1) * BATCH + b];
    float2 s_last = *(const float2*)&sxy[((size_t)(len - 1) * BATCH + b) * 2];
    const float c1 = 6.28318530717958647692f / 86400.0f;  // 2*pi/DAY
    const float c2 = 0.1f / 86400.0f;                     // LAMBDA_T/DAY
    float acc = 0.0f;
    for (int s = 0; s < S_LEN; s++) {
        float dt = t_last - t[(size_t)s * BATCH + b];
        float2 sv = *(const float2*)&sxy[((size_t)s * BATCH + b) * 2];
        float dx = s_last.x - sv.x, dy = s_last.y - sv.y;
        float ds = sqrtf(dx * dx + dy * dy);
        float ft = (cosf(dt * c1) + 1.0f) * 0.5f * expf(-dt * c2);
        float fs = expf(-ds * 1000.0f);
        float wv = (s < len) ? (ft * fs + 1e-10f) : 0.0f;
        w[(size_t)s * BATCH + b] = wv;
        acc += wv;
    }
    wsum[b] = acc;
}

// ---------------- tf32 helpers ----------------
__device__ __forceinline__ uint32_t f2tf(float x)
{
    uint32_t r;
    asm("cvt.rna.tf32.f32 %0, %1;" : "=r"(r) : "f"(x));
    return r;
}

// ---------------- kernel 2/4: tf32 GEMM  C[M,N] = A[M,K] * B[N,K]^T + bias ----
// A row-major (optionally row-gathered through gidx), B row-major [N,K].
// Tiles: CTA 128x128x32, 8 warps as 2(m) x 4(n), warp tile 64x32, mma m16n8k8.
template <bool GATHER, bool NBOUND>
__global__ void __launch_bounds__(256, 2)
gemm_tf32(const float* __restrict__ A, const int* __restrict__ gidx,
          const float* __restrict__ Bm,
          const float* __restrict__ bias1, const float* __restrict__ bias2,
          float* __restrict__ C, int M, int N, int K)
{
    const int PAD = 36;                 // floats per smem row (conflict-free frags)
    __shared__ uint32_t sA[128 * PAD];
    __shared__ uint32_t sB[128 * PAD];

    int tid  = threadIdx.x;
    int lane = tid & 31, warp = tid >> 5;
    int wm = (warp & 1) << 6;           // 0 / 64
    int wn = (warp >> 1) << 5;          // 0 / 32 / 64 / 96
    int g  = lane >> 2, tg = lane & 3;
    int m0 = blockIdx.x * 128;
    int n0 = blockIdx.y * 128;

    float acc[4][4][4];
#pragma unroll
    for (int a = 0; a < 4; a++)
#pragma unroll
        for (int b = 0; b < 4; b++)
#pragma unroll
            for (int c = 0; c < 4; c++) acc[a][b][c] = 0.0f;

    int nChunks = K >> 5;
    for (int kc = 0; kc < nChunks; kc++) {
        int k0 = kc << 5;
        // ---- global -> smem (convert to tf32 once) ----
#pragma unroll
        for (int q = 0; q < 4; q++) {
            int f4  = q * 256 + tid;
            int row = f4 >> 3;
            int c4  = (f4 & 7) << 2;
            {   // A tile
                long arow = GATHER ? (long)gidx[m0 + row] : (long)(m0 + row);
                float4 v = *(const float4*)(A + arow * (long)K + k0 + c4);
                uint4 u = make_uint4(f2tf(v.x), f2tf(v.y), f2tf(v.z), f2tf(v.w));
                *(uint4*)&sA[row * PAD + c4] = u;
            }
            {   // B tile
                int nrow = n0 + row;
                uint4 u;
                if (NBOUND && nrow >= N) {
                    u = make_uint4(0u, 0u, 0u, 0u);
                } else {
                    float4 v = *(const float4*)(Bm + (long)nrow * K + k0 + c4);
                    u = make_uint4(f2tf(v.x), f2tf(v.y), f2tf(v.z), f2tf(v.w));
                }
                *(uint4*)&sB[row * PAD + c4] = u;
            }
        }
        __syncthreads();
        // ---- compute 4 k-steps of 8 ----
#pragma unroll
        for (int ks = 0; ks < 4; ks++) {
            int kk = ks << 3;
            uint32_t af[4][4];
            uint32_t bf[4][2];
#pragma unroll
            for (int mf = 0; mf < 4; mf++) {
                int r = wm + (mf << 4);
                af[mf][0] = sA[(r + g)     * PAD + kk + tg];
                af[mf][1] = sA[(r + g + 8) * PAD + kk + tg];
                af[mf][2] = sA[(r + g)     * PAD + kk + tg + 4];
                af[mf][3] = sA[(r + g + 8) * PAD + kk + tg + 4];
            }
#pragma unroll
            for (int nf = 0; nf < 4; nf++) {
                int r = wn + (nf << 3);
                bf[nf][0] = sB[(r + g) * PAD + kk + tg];
                bf[nf][1] = sB[(r + g) * PAD + kk + tg + 4];
            }
#pragma unroll
            for (int mf = 0; mf < 4; mf++)
#pragma unroll
                for (int nf = 0; nf < 4; nf++)
                    asm volatile(
                        "mma.sync.aligned.m16n8k8.row.col.f32.tf32.tf32.f32 "
                        "{%0,%1,%2,%3}, {%4,%5,%6,%7}, {%8,%9}, {%0,%1,%2,%3};"
                        : "+f"(acc[mf][nf][0]), "+f"(acc[mf][nf][1]),
                          "+f"(acc[mf][nf][2]), "+f"(acc[mf][nf][3])
                        : "r"(af[mf][0]), "r"(af[mf][1]),
                          "r"(af[mf][2]), "r"(af[mf][3]),
                          "r"(bf[nf][0]), "r"(bf[nf][1]));
        }
        __syncthreads();
    }

    // ---- epilogue: bias + store ----
#pragma unroll
    for (int mf = 0; mf < 4; mf++) {
        int r0 = m0 + wm + (mf << 4) + g;
#pragma unroll
        for (int nf = 0; nf < 4; nf++) {
            int col = n0 + wn + (nf << 3) + (tg << 1);
            if (!NBOUND || col < N) {   // col even, N even -> pair safe
                float bv0 = 0.0f, bv1 = 0.0f;
                if (bias1) { bv0 += bias1[col]; bv1 += bias1[col + 1]; }
                if (bias2) { bv0 += bias2[col]; bv1 += bias2[col + 1]; }
                float2 v0 = make_float2(acc[mf][nf][0] + bv0, acc[mf][nf][1] + bv1);
                float2 v1 = make_float2(acc[mf][nf][2] + bv0, acc[mf][nf][3] + bv1);
                *(float2*)(C + (long)r0 * N + col)       = v0;
                *(float2*)(C + (long)(r0 + 8) * N + col) = v1;
            }
        }
    }
}

// ---------------- kernel 3: serial RNN + fused weighted pooling ----------------
// CTA owns NB batch rows; thread tid owns output unit i. W_hh in smem (132-pad:
// LDS.128 4-phase conflict-free), h double-buffered in smem, E pre-projected.
__global__ void __launch_bounds__(128)
rnn_pool_kernel(const float* __restrict__ E, const float* __restrict__ W_hh,
                const float* __restrict__ w, const float* __restrict__ wsum,
                const float* __restrict__ h0,
                const float* __restrict__ W_user, const int* __restrict__ au,
                float* __restrict__ outpu)
{
    extern __shared__ float sm[];
    float* Wsm = sm;                        // 128 * 132
    float* hsm = sm + 128 * 132;            // 2 * NB * 128
    float* wst = hsm + 2 * NB * 128;        // NB

    int tid = threadIdx.x;
    int b0  = blockIdx.x * NB;

    // load W_hh (row i = output unit), padded rows
    for (int i = 0; i < 128; i++)
        Wsm[i * 132 + tid] = W_hh[i * 128 + tid];

    // init hidden state from input h
#pragma unroll
    for (int bb = 0; bb < NB; bb++) {
        int b = min(b0 + bb, BATCH - 1);
        hsm[bb * 128 + tid] = h0[(size_t)b * HID + tid];
    }
    float acc[NB];
#pragma unroll
    for (int bb = 0; bb < NB; bb++) acc[bb] = 0.0f;
    __syncthreads();

    int cur = 0;
    for (int s = 0; s < S_LEN; s++) {
        if (tid < NB) wst[tid] = w[(size_t)s * BATCH + min(b0 + tid, BATCH - 1)];

        float pre[NB];
#pragma unroll
        for (int bb = 0; bb < NB; bb++) {
            int b = min(b0 + bb, BATCH - 1);
            pre[bb] = E[((size_t)s * BATCH + b) * HID + tid];  // biases folded in
        }
        const float* hc = hsm + cur * NB * 128;
#pragma unroll 4
        for (int j = 0; j < 128; j += 4) {
            float4 w4 = *(const float4*)(Wsm + tid * 132 + j);
#pragma unroll
            for (int bb = 0; bb < NB; bb++) {
                float4 h4 = *(const float4*)(hc + bb * 128 + j);
                pre[bb] = fmaf(h4.x, w4.x, pre[bb]);
                pre[bb] = fmaf(h4.y, w4.y, pre[bb]);
                pre[bb] = fmaf(h4.z, w4.z, pre[bb]);
                pre[bb] = fmaf(h4.w, w4.w, pre[bb]);
            }
        }
        __syncthreads();
        float* hn = hsm + (cur ^ 1) * NB * 128;
#pragma unroll
        for (int bb = 0; bb < NB; bb++) {
            float hv = tanhf(pre[bb]);
            hn[bb * 128 + tid] = hv;
            acc[bb] = fmaf(wst[bb], hv, acc[bb]);
        }
        cur ^= 1;
        __syncthreads();
    }

    // epilogue: out_w = acc/wsum ; concat user embedding
#pragma unroll
    for (int bb = 0; bb < NB; bb++) {
        int b = b0 + bb;
        if (b < BATCH) {
            float inv = 1.0f / wsum[b];
            outpu[(size_t)b * 256 + tid]       = acc[bb] * inv;
            outpu[(size_t)b * 256 + 128 + tid] = W_user[(size_t)au[b] * HID + tid];
        }
    }
}

// ---------------- launch ----------------
extern "C" void kernel_launch(void* const* d_in, const int* in_sizes, int n_in,
                              void* d_out, int out_size)
{
    const int*   x      = (const int*)  d_in[0];
    const float* t      = (const float*)d_in[1];
    const float* sxy    = (const float*)d_in[2];
    // d_in[3] = y_t, d_in[4] = y_s : unused
    const float* h0     = (const float*)d_in[5];
    const int*   au     = (const int*)  d_in[6];
    const int*   len    = (const int*)  d_in[7];
    const float* W_enc  = (const float*)d_in[8];
    const float* W_user = (const float*)d_in[9];
    const float* W_ih   = (const float*)d_in[10];
    const float* W_hh   = (const float*)d_in[11];
    const float* b_ih   = (const float*)d_in[12];
    const float* b_hh   = (const float*)d_in[13];
    const float* W_fc   = (const float*)d_in[14];
    const float* b_fc   = (const float*)d_in[15];
    float* out = (float*)d_out;

    float *E, *w, *wsum, *outpu;
    cudaGetSymbolAddress((void**)&E,     g_E);
    cudaGetSymbolAddress((void**)&w,     g_w);
    cudaGetSymbolAddress((void**)&wsum,  g_wsum);
    cudaGetSymbolAddress((void**)&outpu, g_outpu);

    // 1) pooling weights
    pool_weights_kernel<<<BATCH / 256, 256>>>(t, sxy, len, w, wsum);

    // 2) E = gather(W_enc, x) @ W_ih^T + b_ih + b_hh   (M=204800, N=128, K=128)
    dim3 gproj(S_LEN * BATCH / 128, 1);
    gemm_tf32<true, false><<<gproj, 256>>>(W_enc, x, W_ih, b_ih, b_hh, E,
                                           S_LEN * BATCH, HID, HID);

    // 3) serial RNN + fused pooling + user concat
    int smem = 128 * 132 * 4 + 2 * NB * 128 * 4 + NB * 4;
    cudaFuncSetAttribute(rnn_pool_kernel,
                         cudaFuncAttributeMaxDynamicSharedMemorySize, smem);
    int nblk = (BATCH + NB - 1) / NB;
    rnn_pool_kernel<<<nblk, 128, smem>>>(E, W_hh, w, wsum, h0, W_user, au, outpu);

    // 4) logits = outpu @ W_fc^T + b_fc   (M=1024, N=100000, K=256)
    //    grid.x = m (fastest) so the 8 CTAs sharing a W_fc tile are coscheduled.
    dim3 gfin(BATCH / 128, (VOCAB + 127) / 128);
    gemm_tf32<false, true><<<gfin, 256>>>(outpu, nullptr, W_fc, b_fc, nullptr, out,
                                          BATCH, VOCAB, 2 * HID);
}